// round 1
// baseline (speedup 1.0000x reference)
#include <cuda_runtime.h>
#include <math.h>

// Problem constants (fixed by the dataset)
#define E_      8
#define D_      1024
#define H_      1024
#define H2_     2048
#define NTOK_   2048
#define NPAIR_  4096

// ---------------- scratch (no allocations allowed; __device__ globals) -----
__device__ int   g_cnt[E_];
__device__ int   g_perm[E_ * NPAIR_];                   // pair ids bucketed by expert
__device__ float g_hg [(size_t)NPAIR_ * H2_];           // 32 MB: x @ W1[e]  (h | gate)
__device__ float g_act[(size_t)NPAIR_ * H_];            // 16 MB: silu(g)*h

// ---------------- kernel 0: zero output + counters --------------------------
__global__ void __launch_bounds__(256) zero_kernel(float4* __restrict__ out) {
    int i = blockIdx.x * 256 + threadIdx.x;            // NTOK*D/4 = 524288 elems
    out[i] = make_float4(0.f, 0.f, 0.f, 0.f);
    if (blockIdx.x == 0 && threadIdx.x < E_) g_cnt[threadIdx.x] = 0;
}

// ---------------- kernel 1: route pairs into per-expert buckets -------------
__global__ void __launch_bounds__(256) route_kernel(const int* __restrict__ idx) {
    int i = blockIdx.x * 256 + threadIdx.x;
    if (i < NPAIR_) {
        int e   = idx[i];
        int pos = atomicAdd(&g_cnt[e], 1);
        g_perm[e * NPAIR_ + pos] = i;
    }
}

// ---------------- GEMM tiling params ----------------------------------------
#define BM 128
#define BN 128
#define BK 8
// 256 threads; each computes an 8x8 micro-tile split as 2x2 of 4x4 float4 chunks
// (row halves at ty*4 and 64+ty*4; col halves at tx*4 and 64+tx*4) to keep
// LDS conflicts low.

// ---------------- kernel 2: hg = gather(x) @ W1[e]  -------------------------
__global__ void __launch_bounds__(256) gemm1_kernel(const float* __restrict__ x,
                                                    const float* __restrict__ W1) {
    const int e     = blockIdx.z;
    const int cnt   = g_cnt[e];
    const int mTile = blockIdx.y;
    if (mTile * BM >= cnt) return;
    const int nTile = blockIdx.x;

    __shared__ float As[BK][BM];
    __shared__ float Bs[BK][BN];

    const int tid  = threadIdx.x;
    const int aRow = tid >> 1;             // 0..127
    const int aCol = (tid & 1) << 2;       // 0 or 4
    const int bRow = tid >> 5;             // 0..7
    const int bCol = (tid & 31) << 2;      // 0..124

    const float* aPtr = nullptr;
    {
        int rg = mTile * BM + aRow;
        if (rg < cnt) {
            int pair = g_perm[e * NPAIR_ + rg];
            aPtr = x + (size_t)(pair >> 1) * D_ + aCol;   // token row of x
        }
    }
    const float* bPtr = W1 + (size_t)e * D_ * H2_ + (size_t)bRow * H2_
                           + (size_t)nTile * BN + bCol;

    const int tx = tid & 15;
    const int ty = tid >> 4;

    float acc[8][8];
    #pragma unroll
    for (int i = 0; i < 8; i++)
        #pragma unroll
        for (int j = 0; j < 8; j++) acc[i][j] = 0.f;

    float4 av = aPtr ? *(const float4*)(aPtr) : make_float4(0,0,0,0);
    float4 bv = *(const float4*)(bPtr);

    for (int k0 = 0; k0 < D_; k0 += BK) {
        As[aCol+0][aRow] = av.x;
        As[aCol+1][aRow] = av.y;
        As[aCol+2][aRow] = av.z;
        As[aCol+3][aRow] = av.w;
        *(float4*)&Bs[bRow][bCol] = bv;
        __syncthreads();
        if (k0 + BK < D_) {                               // prefetch next K slab
            av = aPtr ? *(const float4*)(aPtr + k0 + BK) : make_float4(0,0,0,0);
            bv = *(const float4*)(bPtr + (size_t)(k0 + BK) * H2_);
        }
        #pragma unroll
        for (int k = 0; k < BK; k++) {
            float ra[8], rb[8];
            *(float4*)&ra[0] = *(const float4*)&As[k][ty*4];
            *(float4*)&ra[4] = *(const float4*)&As[k][64 + ty*4];
            *(float4*)&rb[0] = *(const float4*)&Bs[k][tx*4];
            *(float4*)&rb[4] = *(const float4*)&Bs[k][64 + tx*4];
            #pragma unroll
            for (int i = 0; i < 8; i++)
                #pragma unroll
                for (int j = 0; j < 8; j++)
                    acc[i][j] += ra[i] * rb[j];
        }
        __syncthreads();
    }

    #pragma unroll
    for (int i = 0; i < 8; i++) {
        int rLoc = (i < 4) ? (ty*4 + i) : (64 + ty*4 + (i - 4));
        int rg   = mTile * BM + rLoc;
        if (rg < cnt) {
            int pair   = g_perm[e * NPAIR_ + rg];
            float* dst = g_hg + (size_t)pair * H2_ + (size_t)nTile * BN;
            *(float4*)(dst + tx*4)      = make_float4(acc[i][0],acc[i][1],acc[i][2],acc[i][3]);
            *(float4*)(dst + 64 + tx*4) = make_float4(acc[i][4],acc[i][5],acc[i][6],acc[i][7]);
        }
    }
}

// ---------------- kernel 3: act = h * silu(g) --------------------------------
__global__ void __launch_bounds__(256) silu_kernel() {
    int i = blockIdx.x * 256 + threadIdx.x;    // NPAIR*H/4 = 1048576 iters
    int p = i >> 8;                            // H/4 = 256 float4 per row
    int j = (i & 255) << 2;
    const float4 hv = *(const float4*)(g_hg + (size_t)p * H2_ + j);
    const float4 gv = *(const float4*)(g_hg + (size_t)p * H2_ + H_ + j);
    float4 a;
    a.x = hv.x * gv.x / (1.f + expf(-gv.x));
    a.y = hv.y * gv.y / (1.f + expf(-gv.y));
    a.z = hv.z * gv.z / (1.f + expf(-gv.z));
    a.w = hv.w * gv.w / (1.f + expf(-gv.w));
    *(float4*)(g_act + (size_t)p * H_ + j) = a;
}

// ---------------- kernel 4: out += p * (gather(act) @ W2[e]) -----------------
__global__ void __launch_bounds__(256) gemm2_kernel(const float* __restrict__ W2,
                                                    const float* __restrict__ pgate,
                                                    float* __restrict__ out) {
    const int e     = blockIdx.z;
    const int cnt   = g_cnt[e];
    const int mTile = blockIdx.y;
    if (mTile * BM >= cnt) return;
    const int nTile = blockIdx.x;

    __shared__ float As[BK][BM];
    __shared__ float Bs[BK][BN];

    const int tid  = threadIdx.x;
    const int aRow = tid >> 1;
    const int aCol = (tid & 1) << 2;
    const int bRow = tid >> 5;
    const int bCol = (tid & 31) << 2;

    const float* aPtr = nullptr;
    {
        int rg = mTile * BM + aRow;
        if (rg < cnt) {
            int pair = g_perm[e * NPAIR_ + rg];
            aPtr = g_act + (size_t)pair * H_ + aCol;      // act row is per-pair
        }
    }
    const float* bPtr = W2 + (size_t)e * H_ * D_ + (size_t)bRow * D_
                           + (size_t)nTile * BN + bCol;

    const int tx = tid & 15;
    const int ty = tid >> 4;

    float acc[8][8];
    #pragma unroll
    for (int i = 0; i < 8; i++)
        #pragma unroll
        for (int j = 0; j < 8; j++) acc[i][j] = 0.f;

    float4 av = aPtr ? *(const float4*)(aPtr) : make_float4(0,0,0,0);
    float4 bv = *(const float4*)(bPtr);

    for (int k0 = 0; k0 < H_; k0 += BK) {
        As[aCol+0][aRow] = av.x;
        As[aCol+1][aRow] = av.y;
        As[aCol+2][aRow] = av.z;
        As[aCol+3][aRow] = av.w;
        *(float4*)&Bs[bRow][bCol] = bv;
        __syncthreads();
        if (k0 + BK < H_) {
            av = aPtr ? *(const float4*)(aPtr + k0 + BK) : make_float4(0,0,0,0);
            bv = *(const float4*)(bPtr + (size_t)(k0 + BK) * D_);
        }
        #pragma unroll
        for (int k = 0; k < BK; k++) {
            float ra[8], rb[8];
            *(float4*)&ra[0] = *(const float4*)&As[k][ty*4];
            *(float4*)&ra[4] = *(const float4*)&As[k][64 + ty*4];
            *(float4*)&rb[0] = *(const float4*)&Bs[k][tx*4];
            *(float4*)&rb[4] = *(const float4*)&Bs[k][64 + tx*4];
            #pragma unroll
            for (int i = 0; i < 8; i++)
                #pragma unroll
                for (int j = 0; j < 8; j++)
                    acc[i][j] += ra[i] * rb[j];
        }
        __syncthreads();
    }

    // Epilogue: weight by gate prob, accumulate into token output.
    // Each out element receives exactly 2 contributions (top-2) -> atomicAdd
    // order cannot change the rounded result (x+y is commutative), so the
    // kernel stays deterministic.
    #pragma unroll
    for (int i = 0; i < 8; i++) {
        int rLoc = (i < 4) ? (ty*4 + i) : (64 + ty*4 + (i - 4));
        int rg   = mTile * BM + rLoc;
        if (rg < cnt) {
            int   pair  = g_perm[e * NPAIR_ + rg];
            int   token = pair >> 1;
            float pc    = pgate[pair];
            float* dst  = out + (size_t)token * D_ + (size_t)nTile * BN;
            #pragma unroll
            for (int j = 0; j < 4; j++) {
                atomicAdd(dst + tx*4 + j,      acc[i][j]   * pc);
                atomicAdd(dst + 64 + tx*4 + j, acc[i][4+j] * pc);
            }
        }
    }
}

// ---------------- launch ------------------------------------------------------
extern "C" void kernel_launch(void* const* d_in, const int* in_sizes, int n_in,
                              void* d_out, int out_size) {
    const float* x   = (const float*)d_in[0];   // [2,1024,1024] f32
    const float* p   = (const float*)d_in[1];   // [2048,2]      f32
    const int*   idx = (const int*)  d_in[2];   // [2048,2]      int32
    const float* W1  = (const float*)d_in[3];   // [8,1024,2048] f32
    const float* W2  = (const float*)d_in[4];   // [8,1024,1024] f32
    float*       out = (float*)d_out;           // [2,1024,1024] f32

    (void)in_sizes; (void)n_in; (void)out_size;

    zero_kernel <<<2048, 256>>>((float4*)out);           // 2M floats + counters
    route_kernel<<<16,   256>>>(idx);                    // 4096 pairs
    gemm1_kernel<<<dim3(H2_/BN, NPAIR_/BM, E_), 256>>>(x, W1);
    silu_kernel <<<4096, 256>>>();                       // NPAIR*H/4 elems
    gemm2_kernel<<<dim3(D_/BN, NPAIR_/BM, E_), 256>>>(W2, p, out);
}

// round 3
// speedup vs baseline: 1.7017x; 1.7017x over previous
#include <cuda_runtime.h>
#include <cuda_bf16.h>
#include <cstdint>
#include <math.h>

// ---------------- problem constants -----------------------------------------
#define E_      8
#define D_      1024
#define H_      1024
#define H2_     2048
#define NTOK_   2048
#define NPAIR_  4096

// ---------------- scratch (__device__ globals; no allocations) --------------
__device__ int   g_cnt[E_];
__device__ int   g_perm[E_ * NPAIR_];
__device__ float g_hg[(size_t)NPAIR_ * H2_];                 // 32 MB fp32
__device__ __nv_bfloat16 g_xhi[(size_t)NTOK_ * D_];
__device__ __nv_bfloat16 g_xlo[(size_t)NTOK_ * D_];
__device__ __nv_bfloat16 g_ahi[(size_t)NPAIR_ * H_];
__device__ __nv_bfloat16 g_alo[(size_t)NPAIR_ * H_];
__device__ __nv_bfloat16 g_w1hi[(size_t)E_ * H2_ * D_];      // W1^T [e][n][k]
__device__ __nv_bfloat16 g_w1lo[(size_t)E_ * H2_ * D_];
__device__ __nv_bfloat16 g_w2hi[(size_t)E_ * D_ * H_];       // W2^T [e][n][k]
__device__ __nv_bfloat16 g_w2lo[(size_t)E_ * D_ * H_];

// ---------------- kernel 0/1: zero + route -----------------------------------
__global__ void __launch_bounds__(256) zero_kernel(float4* __restrict__ out) {
    int i = blockIdx.x * 256 + threadIdx.x;
    out[i] = make_float4(0.f, 0.f, 0.f, 0.f);
    if (blockIdx.x == 0 && threadIdx.x < E_) g_cnt[threadIdx.x] = 0;
}
__global__ void __launch_bounds__(256) route_kernel(const int* __restrict__ idx) {
    int i = blockIdx.x * 256 + threadIdx.x;
    if (i < NPAIR_) {
        int e = idx[i];
        int pos = atomicAdd(&g_cnt[e], 1);
        g_perm[e * NPAIR_ + pos] = i;
    }
}

// ---------------- kernel 2: convert x -> bf16 hi/lo --------------------------
__global__ void __launch_bounds__(256) cvt_x_kernel(const float4* __restrict__ x) {
    int i = blockIdx.x * 256 + threadIdx.x;              // 512K float4
    float4 v = x[i];
    __nv_bfloat162 h0 = __floats2bfloat162_rn(v.x, v.y);
    __nv_bfloat162 h1 = __floats2bfloat162_rn(v.z, v.w);
    __nv_bfloat162 l0 = __floats2bfloat162_rn(v.x - __low2float(h0), v.y - __high2float(h0));
    __nv_bfloat162 l1 = __floats2bfloat162_rn(v.z - __low2float(h1), v.w - __high2float(h1));
    ((__nv_bfloat162*)g_xhi)[2 * i]     = h0;
    ((__nv_bfloat162*)g_xhi)[2 * i + 1] = h1;
    ((__nv_bfloat162*)g_xlo)[2 * i]     = l0;
    ((__nv_bfloat162*)g_xlo)[2 * i + 1] = l1;
}

// ---------------- kernel 3: transpose + split W -> [e][n][k] bf16 hi/lo ------
__global__ void transpose_cvt_kernel(const float* __restrict__ src, int which,
                                     int K, int N) {
    __shared__ float t[32][33];
    __nv_bfloat16* dhi = (which == 1) ? g_w1hi : g_w2hi;
    __nv_bfloat16* dlo = (which == 1) ? g_w1lo : g_w2lo;
    int e = blockIdx.z;
    const float* s = src + (size_t)e * K * N;
    size_t dbase = (size_t)e * K * N;
    int n0 = blockIdx.x * 32, k0 = blockIdx.y * 32;
    #pragma unroll
    for (int r = 0; r < 32; r += 8)
        t[threadIdx.y + r][threadIdx.x] = s[(size_t)(k0 + threadIdx.y + r) * N + n0 + threadIdx.x];
    __syncthreads();
    #pragma unroll
    for (int r = 0; r < 32; r += 8) {
        int n = n0 + threadIdx.y + r;
        float v = t[threadIdx.x][threadIdx.y + r];
        __nv_bfloat16 h = __float2bfloat16(v);
        __nv_bfloat16 l = __float2bfloat16(v - __bfloat162float(h));
        size_t o = dbase + (size_t)n * K + k0 + threadIdx.x;
        dhi[o] = h; dlo[o] = l;
    }
}

// ---------------- kernel 5: silu + convert to bf16 hi/lo ---------------------
__global__ void __launch_bounds__(256) silu_cvt_kernel() {
    int i = blockIdx.x * 256 + threadIdx.x;              // NPAIR*H/4 = 1M
    int p = i >> 8;
    int j = (i & 255) << 2;
    float4 hv = *(const float4*)(g_hg + (size_t)p * H2_ + j);
    float4 gv = *(const float4*)(g_hg + (size_t)p * H2_ + H_ + j);
    float a0 = hv.x * gv.x / (1.f + expf(-gv.x));
    float a1 = hv.y * gv.y / (1.f + expf(-gv.y));
    float a2 = hv.z * gv.z / (1.f + expf(-gv.z));
    float a3 = hv.w * gv.w / (1.f + expf(-gv.w));
    __nv_bfloat162 h0 = __floats2bfloat162_rn(a0, a1);
    __nv_bfloat162 h1 = __floats2bfloat162_rn(a2, a3);
    __nv_bfloat162 l0 = __floats2bfloat162_rn(a0 - __low2float(h0), a1 - __high2float(h0));
    __nv_bfloat162 l1 = __floats2bfloat162_rn(a2 - __low2float(h1), a3 - __high2float(h1));
    size_t o = ((size_t)p * H_ + j) >> 1;
    ((__nv_bfloat162*)g_ahi)[o]     = h0;
    ((__nv_bfloat162*)g_ahi)[o + 1] = h1;
    ((__nv_bfloat162*)g_alo)[o]     = l0;
    ((__nv_bfloat162*)g_alo)[o + 1] = l1;
}

// ---------------- warp-level bf16 mma helper ----------------------------------
__device__ __forceinline__ void mma16816(float* c, const uint32_t* a, const uint32_t* b) {
    asm volatile(
        "mma.sync.aligned.m16n8k16.row.col.f32.bf16.bf16.f32 "
        "{%0,%1,%2,%3}, {%4,%5,%6,%7}, {%8,%9}, {%0,%1,%2,%3};"
        : "+f"(c[0]), "+f"(c[1]), "+f"(c[2]), "+f"(c[3])
        : "r"(a[0]), "r"(a[1]), "r"(a[2]), "r"(a[3]), "r"(b[0]), "r"(b[1]));
}

// ---------------- GEMM: 128x128 CTA tile, 8 warps (2x4), warp tile 64x32 -----
// SMEM (dynamic): rowoff[128] int @0; stage s @512 + s*40960:
//   Ah[128][40] bf16, Al, Bh, Bl (5120 elems / 10240 B each; stride 40 is
//   bank-exact conflict-free for the 4B fragment loads: bank=(20r+c)%32).
#define KC      32
#define STRIDE  40
#define ARR_EL  (128 * STRIDE)
#define STAGE_B (4 * ARR_EL * 2)
#define SMEM_DYN (512 + 2 * STAGE_B)

__global__ void __launch_bounds__(256, 1) moe_gemm_kernel(
    const float* __restrict__ pgate, float* __restrict__ out, int mode, int Ntot)
{
    const int e     = blockIdx.z;
    const int cnt   = g_cnt[e];
    const int mTile = blockIdx.y;
    if (mTile * 128 >= cnt) return;
    const int nTile = blockIdx.x;

    extern __shared__ char smem[];
    int* rowoff = (int*)smem;
    __nv_bfloat16* stage0 = (__nv_bfloat16*)(smem + 512);

    const int tid  = threadIdx.x;
    const int wid  = tid >> 5;
    const int lane = tid & 31;
    const int wm   = wid & 1;          // 0..1
    const int wn   = wid >> 1;         // 0..3

    const __nv_bfloat16* Ahi = (mode == 1) ? g_xhi  : g_ahi;
    const __nv_bfloat16* Alo = (mode == 1) ? g_xlo  : g_alo;
    const __nv_bfloat16* Bhi = (mode == 1) ? g_w1hi : g_w2hi;
    const __nv_bfloat16* Blo = (mode == 1) ? g_w1lo : g_w2lo;
    const size_t boff = ((size_t)e * Ntot + (size_t)nTile * 128) * 1024;
    Bhi += boff; Blo += boff;

    if (tid < 128) {
        int rg = mTile * 128 + tid;
        int off = -1;
        if (rg < cnt) {
            int pair = g_perm[e * NPAIR_ + rg];
            off = (mode == 1) ? ((pair >> 1) << 10) : (pair << 10);
        }
        rowoff[tid] = off;
    }
    __syncthreads();

    // staging registers: 2 items/thread x 4 arrays
    uint4 rg_[8];
    const uint4 z4 = make_uint4(0, 0, 0, 0);

    auto load_g = [&](int k0) {
        #pragma unroll
        for (int j = 0; j < 2; j++) {
            int item = tid + 256 * j;
            int row  = item >> 2;
            int col  = (item & 3) * 8;
            int ao   = rowoff[row];
            if (ao >= 0) {
                rg_[j]     = *(const uint4*)(Ahi + ao + k0 + col);
                rg_[2 + j] = *(const uint4*)(Alo + ao + k0 + col);
            } else {
                rg_[j] = z4; rg_[2 + j] = z4;
            }
            size_t bo = (size_t)row * 1024 + k0 + col;
            rg_[4 + j] = *(const uint4*)(Bhi + bo);
            rg_[6 + j] = *(const uint4*)(Blo + bo);
        }
    };
    auto store_s = [&](int buf) {
        __nv_bfloat16* base = stage0 + buf * (4 * ARR_EL);
        #pragma unroll
        for (int j = 0; j < 2; j++) {
            int item = tid + 256 * j;
            int o = (item >> 2) * STRIDE + (item & 3) * 8;
            *(uint4*)(base + o)              = rg_[j];
            *(uint4*)(base + ARR_EL + o)     = rg_[2 + j];
            *(uint4*)(base + 2 * ARR_EL + o) = rg_[4 + j];
            *(uint4*)(base + 3 * ARR_EL + o) = rg_[6 + j];
        }
    };

    float acc[4][4][4];
    #pragma unroll
    for (int i = 0; i < 4; i++)
        #pragma unroll
        for (int j = 0; j < 4; j++)
            #pragma unroll
            for (int q = 0; q < 4; q++) acc[i][j][q] = 0.f;

    const int gr  = lane >> 2;
    const int lc2 = (lane & 3) * 2;

    load_g(0);
    store_s(0);
    __syncthreads();

    const int NCH = 1024 / KC;     // 32 chunks
    for (int c = 0; c < NCH; c++) {
        if (c + 1 < NCH) load_g((c + 1) * KC);

        const __nv_bfloat16* base = stage0 + (c & 1) * (4 * ARR_EL);
        const __nv_bfloat16* Ah = base;
        const __nv_bfloat16* Al = base + ARR_EL;
        const __nv_bfloat16* Bh = base + 2 * ARR_EL;
        const __nv_bfloat16* Bl = base + 3 * ARR_EL;

        #pragma unroll
        for (int kk = 0; kk < KC; kk += 16) {
            uint32_t ah[4][4], al[4][4], bh[4][2], bl[4][2];
            #pragma unroll
            for (int mf = 0; mf < 4; mf++) {
                int r0 = (wm * 64 + mf * 16 + gr) * STRIDE;
                int r1 = r0 + 8 * STRIDE;
                ah[mf][0] = *(const uint32_t*)(Ah + r0 + kk + lc2);
                ah[mf][1] = *(const uint32_t*)(Ah + r1 + kk + lc2);
                ah[mf][2] = *(const uint32_t*)(Ah + r0 + kk + 8 + lc2);
                ah[mf][3] = *(const uint32_t*)(Ah + r1 + kk + 8 + lc2);
                al[mf][0] = *(const uint32_t*)(Al + r0 + kk + lc2);
                al[mf][1] = *(const uint32_t*)(Al + r1 + kk + lc2);
                al[mf][2] = *(const uint32_t*)(Al + r0 + kk + 8 + lc2);
                al[mf][3] = *(const uint32_t*)(Al + r1 + kk + 8 + lc2);
            }
            #pragma unroll
            for (int nf = 0; nf < 4; nf++) {
                int nb = (wn * 32 + nf * 8 + gr) * STRIDE;
                bh[nf][0] = *(const uint32_t*)(Bh + nb + kk + lc2);
                bh[nf][1] = *(const uint32_t*)(Bh + nb + kk + 8 + lc2);
                bl[nf][0] = *(const uint32_t*)(Bl + nb + kk + lc2);
                bl[nf][1] = *(const uint32_t*)(Bl + nb + kk + 8 + lc2);
            }
            #pragma unroll
            for (int mf = 0; mf < 4; mf++)
                #pragma unroll
                for (int nf = 0; nf < 4; nf++) {
                    mma16816(acc[mf][nf], ah[mf], bh[nf]);
                    mma16816(acc[mf][nf], ah[mf], bl[nf]);
                    mma16816(acc[mf][nf], al[mf], bh[nf]);
                }
        }

        if (c + 1 < NCH) {
            store_s((c + 1) & 1);
            __syncthreads();
        }
    }

    // ---- epilogue ----
    #pragma unroll
    for (int mf = 0; mf < 4; mf++) {
        #pragma unroll
        for (int half = 0; half < 2; half++) {
            int r  = wm * 64 + mf * 16 + gr + half * 8;
            int rg2 = mTile * 128 + r;
            if (rg2 < cnt) {
                int pair = g_perm[e * NPAIR_ + rg2];
                if (mode == 1) {
                    float* dst = g_hg + (size_t)pair * H2_ + (size_t)nTile * 128;
                    #pragma unroll
                    for (int nf = 0; nf < 4; nf++) {
                        int n = wn * 32 + nf * 8 + lc2;
                        *(float2*)(dst + n) = make_float2(acc[mf][nf][half * 2],
                                                          acc[mf][nf][half * 2 + 1]);
                    }
                } else {
                    float pc = pgate[pair];
                    float* dst = out + (size_t)(pair >> 1) * D_ + (size_t)nTile * 128;
                    #pragma unroll
                    for (int nf = 0; nf < 4; nf++) {
                        int n = wn * 32 + nf * 8 + lc2;
                        atomicAdd(dst + n,     acc[mf][nf][half * 2]     * pc);
                        atomicAdd(dst + n + 1, acc[mf][nf][half * 2 + 1] * pc);
                    }
                }
            }
        }
    }
}

// ---------------- launch ------------------------------------------------------
extern "C" void kernel_launch(void* const* d_in, const int* in_sizes, int n_in,
                              void* d_out, int out_size) {
    const float* x   = (const float*)d_in[0];   // [2,1024,1024] f32
    const float* p   = (const float*)d_in[1];   // [2048,2]      f32
    const int*   idx = (const int*)  d_in[2];   // [2048,2]      int32
    const float* W1  = (const float*)d_in[3];   // [8,1024,2048] f32
    const float* W2  = (const float*)d_in[4];   // [8,1024,1024] f32
    float*       out = (float*)d_out;           // [2,1024,1024] f32
    (void)in_sizes; (void)n_in; (void)out_size;

    cudaFuncSetAttribute(moe_gemm_kernel,
                         cudaFuncAttributeMaxDynamicSharedMemorySize, SMEM_DYN);

    zero_kernel <<<2048, 256>>>((float4*)out);
    route_kernel<<<16,   256>>>(idx);
    cvt_x_kernel<<<2048, 256>>>((const float4*)x);
    transpose_cvt_kernel<<<dim3(H2_/32, D_/32, E_), dim3(32, 8)>>>(W1, 1, D_, H2_);
    transpose_cvt_kernel<<<dim3(H_/32,  H_/32, E_), dim3(32, 8)>>>(W2, 2, H_, H_);
    moe_gemm_kernel<<<dim3(H2_/128, NPAIR_/128, E_), 256, SMEM_DYN>>>(p, out, 1, H2_);
    silu_cvt_kernel<<<4096, 256>>>();
    moe_gemm_kernel<<<dim3(D_/128, NPAIR_/128, E_), 256, SMEM_DYN>>>(p, out, 2, D_);
}

// round 4
// speedup vs baseline: 1.7927x; 1.0535x over previous
#include <cuda_runtime.h>
#include <cuda_bf16.h>
#include <cstdint>
#include <math.h>

// ---------------- problem constants -----------------------------------------
#define E_      8
#define D_      1024
#define H_      1024
#define H2_     2048
#define NTOK_   2048
#define NPAIR_  4096

// ---------------- scratch (__device__ globals; no allocations) --------------
__device__ int   g_cnt[E_];
__device__ int   g_perm[E_ * NPAIR_];
__device__ float g_hg[(size_t)NPAIR_ * H2_];                 // 32 MB fp32
__device__ __nv_bfloat16 g_xhi[(size_t)NTOK_ * D_];
__device__ __nv_bfloat16 g_xlo[(size_t)NTOK_ * D_];
__device__ __nv_bfloat16 g_ahi[(size_t)NPAIR_ * H_];
__device__ __nv_bfloat16 g_alo[(size_t)NPAIR_ * H_];
__device__ __nv_bfloat16 g_w1hi[(size_t)E_ * H2_ * D_];      // W1^T [e][n][k]
__device__ __nv_bfloat16 g_w1lo[(size_t)E_ * H2_ * D_];
__device__ __nv_bfloat16 g_w2hi[(size_t)E_ * D_ * H_];       // W2^T [e][n][k]
__device__ __nv_bfloat16 g_w2lo[(size_t)E_ * D_ * H_];

// ---------------- kernel 0/1: zero + route -----------------------------------
__global__ void __launch_bounds__(256) zero_kernel(float4* __restrict__ out) {
    int i = blockIdx.x * 256 + threadIdx.x;
    out[i] = make_float4(0.f, 0.f, 0.f, 0.f);
    if (blockIdx.x == 0 && threadIdx.x < E_) g_cnt[threadIdx.x] = 0;
}
__global__ void __launch_bounds__(256) route_kernel(const int* __restrict__ idx) {
    int i = blockIdx.x * 256 + threadIdx.x;
    if (i < NPAIR_) {
        int e = idx[i];
        int pos = atomicAdd(&g_cnt[e], 1);
        g_perm[e * NPAIR_ + pos] = i;
    }
}

// ---------------- kernel 2: convert x -> bf16 hi/lo --------------------------
__global__ void __launch_bounds__(256) cvt_x_kernel(const float4* __restrict__ x) {
    int i = blockIdx.x * 256 + threadIdx.x;              // 512K float4
    float4 v = x[i];
    __nv_bfloat162 h0 = __floats2bfloat162_rn(v.x, v.y);
    __nv_bfloat162 h1 = __floats2bfloat162_rn(v.z, v.w);
    __nv_bfloat162 l0 = __floats2bfloat162_rn(v.x - __low2float(h0), v.y - __high2float(h0));
    __nv_bfloat162 l1 = __floats2bfloat162_rn(v.z - __low2float(h1), v.w - __high2float(h1));
    ((__nv_bfloat162*)g_xhi)[2 * i]     = h0;
    ((__nv_bfloat162*)g_xhi)[2 * i + 1] = h1;
    ((__nv_bfloat162*)g_xlo)[2 * i]     = l0;
    ((__nv_bfloat162*)g_xlo)[2 * i + 1] = l1;
}

// ---------------- kernel 3: transpose + split W -> [e][n][k] bf16 hi/lo ------
__global__ void transpose_cvt_kernel(const float* __restrict__ src, int which,
                                     int K, int N) {
    __shared__ float t[32][33];
    __nv_bfloat16* dhi = (which == 1) ? g_w1hi : g_w2hi;
    __nv_bfloat16* dlo = (which == 1) ? g_w1lo : g_w2lo;
    int e = blockIdx.z;
    const float* s = src + (size_t)e * K * N;
    size_t dbase = (size_t)e * K * N;
    int n0 = blockIdx.x * 32, k0 = blockIdx.y * 32;
    #pragma unroll
    for (int r = 0; r < 32; r += 8)
        t[threadIdx.y + r][threadIdx.x] = s[(size_t)(k0 + threadIdx.y + r) * N + n0 + threadIdx.x];
    __syncthreads();
    #pragma unroll
    for (int r = 0; r < 32; r += 8) {
        int n = n0 + threadIdx.y + r;
        float v = t[threadIdx.x][threadIdx.y + r];
        __nv_bfloat16 h = __float2bfloat16(v);
        __nv_bfloat16 l = __float2bfloat16(v - __bfloat162float(h));
        size_t o = dbase + (size_t)n * K + k0 + threadIdx.x;
        dhi[o] = h; dlo[o] = l;
    }
}

// ---------------- kernel 5: silu + convert to bf16 hi/lo ---------------------
__global__ void __launch_bounds__(256) silu_cvt_kernel() {
    int i = blockIdx.x * 256 + threadIdx.x;              // NPAIR*H/4 = 1M
    int p = i >> 8;
    int j = (i & 255) << 2;
    float4 hv = *(const float4*)(g_hg + (size_t)p * H2_ + j);
    float4 gv = *(const float4*)(g_hg + (size_t)p * H2_ + H_ + j);
    float a0 = hv.x * gv.x / (1.f + expf(-gv.x));
    float a1 = hv.y * gv.y / (1.f + expf(-gv.y));
    float a2 = hv.z * gv.z / (1.f + expf(-gv.z));
    float a3 = hv.w * gv.w / (1.f + expf(-gv.w));
    __nv_bfloat162 h0 = __floats2bfloat162_rn(a0, a1);
    __nv_bfloat162 h1 = __floats2bfloat162_rn(a2, a3);
    __nv_bfloat162 l0 = __floats2bfloat162_rn(a0 - __low2float(h0), a1 - __high2float(h0));
    __nv_bfloat162 l1 = __floats2bfloat162_rn(a2 - __low2float(h1), a3 - __high2float(h1));
    size_t o = ((size_t)p * H_ + j) >> 1;
    ((__nv_bfloat162*)g_ahi)[o]     = h0;
    ((__nv_bfloat162*)g_ahi)[o + 1] = h1;
    ((__nv_bfloat162*)g_alo)[o]     = l0;
    ((__nv_bfloat162*)g_alo)[o + 1] = l1;
}

// ---------------- warp-level helpers ------------------------------------------
__device__ __forceinline__ void mma16816(float* c, const uint32_t* a, const uint32_t* b) {
    asm volatile(
        "mma.sync.aligned.m16n8k16.row.col.f32.bf16.bf16.f32 "
        "{%0,%1,%2,%3}, {%4,%5,%6,%7}, {%8,%9}, {%0,%1,%2,%3};"
        : "+f"(c[0]), "+f"(c[1]), "+f"(c[2]), "+f"(c[3])
        : "r"(a[0]), "r"(a[1]), "r"(a[2]), "r"(a[3]), "r"(b[0]), "r"(b[1]));
}
__device__ __forceinline__ void ldsm4(uint32_t* d, uint32_t a) {
    asm volatile("ldmatrix.sync.aligned.m8n8.x4.shared.b16 {%0,%1,%2,%3}, [%4];"
                 : "=r"(d[0]), "=r"(d[1]), "=r"(d[2]), "=r"(d[3]) : "r"(a));
}
__device__ __forceinline__ void cpasync16(uint32_t dst, const void* src, int sz) {
    asm volatile("cp.async.cg.shared.global [%0], [%1], 16, %2;"
                 :: "r"(dst), "l"(src), "r"(sz) : "memory");
}
__device__ __forceinline__ uint32_t smem_u32(const void* p) {
    uint32_t a;
    asm("{ .reg .u64 t; cvta.to.shared.u64 t, %1; cvt.u32.u64 %0, t; }" : "=r"(a) : "l"(p));
    return a;
}

// ---------------- GEMM: 128x128 CTA, 8 warps (2x4), warp 64x32, KC=64 --------
// SMEM: rowoff[128] @0; 3 stages @1024 + s*65536:
//   each stage: Ah(16K) Al(16K) Bh(16K) Bl(16K); rows of 128B, 16B-chunk
//   swizzle (chunk ^ (row&7)) -> conflict-free cp.async stores + ldmatrix.
#define KC       64
#define STAGE_B  65536
#define NSTAGE   3
#define SMEM_DYN (1024 + NSTAGE * STAGE_B)

__global__ void __launch_bounds__(256, 1) moe_gemm_kernel(
    const float* __restrict__ pgate, float* __restrict__ out, int mode, int Ntot)
{
    const int e     = blockIdx.z;
    const int cnt   = g_cnt[e];
    const int mTile = blockIdx.y;
    if (mTile * 128 >= cnt) return;
    const int nTile = blockIdx.x;

    extern __shared__ char smem[];
    int* rowoff = (int*)smem;
    const uint32_t sbase = smem_u32(smem);

    const int tid  = threadIdx.x;
    const int wid  = tid >> 5;
    const int lane = tid & 31;
    const int wm   = wid & 1;          // 0..1
    const int wn   = wid >> 1;         // 0..3

    const __nv_bfloat16* Ahi = (mode == 1) ? g_xhi  : g_ahi;
    const __nv_bfloat16* Alo = (mode == 1) ? g_xlo  : g_alo;
    const __nv_bfloat16* Bhi = (mode == 1) ? g_w1hi : g_w2hi;
    const __nv_bfloat16* Blo = (mode == 1) ? g_w1lo : g_w2lo;
    const size_t boff = ((size_t)e * Ntot + (size_t)nTile * 128) * 1024;
    Bhi += boff; Blo += boff;

    if (tid < 128) {
        int rg = mTile * 128 + tid;
        int off = -1;
        if (rg < cnt) {
            int pair = g_perm[e * NPAIR_ + rg];
            off = (mode == 1) ? ((pair >> 1) << 10) : (pair << 10);
        }
        rowoff[tid] = off;
    }
    __syncthreads();

    // ---- cp.async stage loader: thread t -> row r=t/2, 4 16B chunks --------
    const int lr  = tid >> 1;
    const int lcb = (tid & 1) * 4;
    const int lrx = lr & 7;
    auto issue_stage = [&](int c) {
        const int k0 = c * KC;
        const uint32_t stb = sbase + 1024 + (c % NSTAGE) * STAGE_B;
        const uint32_t dA = stb + lr * 128;
        int ao = rowoff[lr];
        int sz = (ao >= 0) ? 16 : 0;
        const __nv_bfloat16* aph = Ahi + (ao >= 0 ? ao : 0) + k0 + lcb * 8;
        const __nv_bfloat16* apl = Alo + (ao >= 0 ? ao : 0) + k0 + lcb * 8;
        const __nv_bfloat16* bph = Bhi + (size_t)lr * 1024 + k0 + lcb * 8;
        const __nv_bfloat16* bpl = Blo + (size_t)lr * 1024 + k0 + lcb * 8;
        #pragma unroll
        for (int i = 0; i < 4; i++) {
            uint32_t sw = (uint32_t)(((lcb + i) ^ lrx) << 4);
            cpasync16(dA + sw,         aph + i * 8, sz);
            cpasync16(dA + 16384 + sw, apl + i * 8, sz);
            cpasync16(dA + 32768 + sw, bph + i * 8, 16);
            cpasync16(dA + 49152 + sw, bpl + i * 8, 16);
        }
        asm volatile("cp.async.commit_group;" ::: "memory");
    };

    // ---- per-lane ldmatrix address bases ------------------------------------
    const int g  = lane >> 3;
    const int r8 = lane & 7;
    uint32_t aRowOff[4], bRowOff[2];
    #pragma unroll
    for (int mf = 0; mf < 4; mf++)
        aRowOff[mf] = (uint32_t)((wm * 64 + mf * 16 + (g & 1) * 8 + r8) * 128);
    #pragma unroll
    for (int j = 0; j < 2; j++)
        bRowOff[j] = (uint32_t)((wn * 32 + j * 16 + (g >> 1) * 8 + r8) * 128);
    const int acadd = g >> 1;
    const int bcadd = g & 1;

    float acc[4][4][4];
    #pragma unroll
    for (int i = 0; i < 4; i++)
        #pragma unroll
        for (int j = 0; j < 4; j++)
            #pragma unroll
            for (int q = 0; q < 4; q++) acc[i][j][q] = 0.f;

    issue_stage(0);
    issue_stage(1);

    const int NCH = 1024 / KC;   // 16
    for (int c = 0; c < NCH; c++) {
        if (c < NCH - 1) asm volatile("cp.async.wait_group 1;" ::: "memory");
        else             asm volatile("cp.async.wait_group 0;" ::: "memory");
        __syncthreads();
        if (c + 2 < NCH) issue_stage(c + 2);

        const uint32_t stb = sbase + 1024 + (c % NSTAGE) * STAGE_B;
        #pragma unroll
        for (int s = 0; s < 4; s++) {
            uint32_t ah[4][4], al[4][4], bh[2][4], bl[2][4];
            const uint32_t asw = (uint32_t)((((s * 2 + acadd) ^ r8) << 4));
            const uint32_t bsw = (uint32_t)((((s * 2 + bcadd) ^ r8) << 4));
            #pragma unroll
            for (int mf = 0; mf < 4; mf++) {
                ldsm4(ah[mf], stb + aRowOff[mf] + asw);
                ldsm4(al[mf], stb + 16384 + aRowOff[mf] + asw);
            }
            #pragma unroll
            for (int j = 0; j < 2; j++) {
                ldsm4(bh[j], stb + 32768 + bRowOff[j] + bsw);
                ldsm4(bl[j], stb + 49152 + bRowOff[j] + bsw);
            }
            #pragma unroll
            for (int mf = 0; mf < 4; mf++)
                #pragma unroll
                for (int nf = 0; nf < 4; nf++) {
                    const int jj = nf >> 1, hh = nf & 1;
                    uint32_t bhp[2] = { bh[jj][2 * hh], bh[jj][2 * hh + 1] };
                    uint32_t blp[2] = { bl[jj][2 * hh], bl[jj][2 * hh + 1] };
                    mma16816(acc[mf][nf], ah[mf], bhp);
                    mma16816(acc[mf][nf], ah[mf], blp);
                    mma16816(acc[mf][nf], al[mf], bhp);
                }
        }
    }

    // ---- epilogue ----
    const int gr  = lane >> 2;
    const int lc2 = (lane & 3) * 2;
    #pragma unroll
    for (int mf = 0; mf < 4; mf++) {
        #pragma unroll
        for (int half = 0; half < 2; half++) {
            int r   = wm * 64 + mf * 16 + gr + half * 8;
            int rg2 = mTile * 128 + r;
            if (rg2 < cnt) {
                int pair = g_perm[e * NPAIR_ + rg2];
                if (mode == 1) {
                    float* dst = g_hg + (size_t)pair * H2_ + (size_t)nTile * 128;
                    #pragma unroll
                    for (int nf = 0; nf < 4; nf++) {
                        int n = wn * 32 + nf * 8 + lc2;
                        *(float2*)(dst + n) = make_float2(acc[mf][nf][half * 2],
                                                          acc[mf][nf][half * 2 + 1]);
                    }
                } else {
                    float pc = pgate[pair];
                    float* dst = out + (size_t)(pair >> 1) * D_ + (size_t)nTile * 128;
                    #pragma unroll
                    for (int nf = 0; nf < 4; nf++) {
                        int n = wn * 32 + nf * 8 + lc2;
                        atomicAdd(dst + n,     acc[mf][nf][half * 2]     * pc);
                        atomicAdd(dst + n + 1, acc[mf][nf][half * 2 + 1] * pc);
                    }
                }
            }
        }
    }
}

// ---------------- launch ------------------------------------------------------
extern "C" void kernel_launch(void* const* d_in, const int* in_sizes, int n_in,
                              void* d_out, int out_size) {
    const float* x   = (const float*)d_in[0];   // [2,1024,1024] f32
    const float* p   = (const float*)d_in[1];   // [2048,2]      f32
    const int*   idx = (const int*)  d_in[2];   // [2048,2]      int32
    const float* W1  = (const float*)d_in[3];   // [8,1024,2048] f32
    const float* W2  = (const float*)d_in[4];   // [8,1024,1024] f32
    float*       out = (float*)d_out;           // [2,1024,1024] f32
    (void)in_sizes; (void)n_in; (void)out_size;

    cudaFuncSetAttribute(moe_gemm_kernel,
                         cudaFuncAttributeMaxDynamicSharedMemorySize, SMEM_DYN);

    zero_kernel <<<2048, 256>>>((float4*)out);
    route_kernel<<<16,   256>>>(idx);
    cvt_x_kernel<<<2048, 256>>>((const float4*)x);
    transpose_cvt_kernel<<<dim3(H2_/32, D_/32, E_), dim3(32, 8)>>>(W1, 1, D_, H2_);
    transpose_cvt_kernel<<<dim3(H_/32,  H_/32, E_), dim3(32, 8)>>>(W2, 2, H_, H_);
    moe_gemm_kernel<<<dim3(H2_/128, NPAIR_/128, E_), 256, SMEM_DYN>>>(p, out, 1, H2_);
    silu_cvt_kernel<<<4096, 256>>>();
    moe_gemm_kernel<<<dim3(D_/128, NPAIR_/128, E_), 256, SMEM_DYN>>>(p, out, 2, D_);
}

// round 5
// speedup vs baseline: 2.3286x; 1.2990x over previous
#include <cuda_runtime.h>
#include <cuda_fp16.h>
#include <cstdint>
#include <math.h>

// ---------------- problem constants -----------------------------------------
#define E_      8
#define D_      1024
#define H_      1024
#define H2_     2048
#define NTOK_   2048
#define NPAIR_  4096

// ---------------- scratch (__device__ globals; no allocations) --------------
__device__ int   g_cnt[E_];
__device__ int   g_perm[E_ * NPAIR_];
__device__ float g_hg[(size_t)NPAIR_ * H2_];                 // 32 MB fp32
__device__ __half g_xhi[(size_t)NTOK_ * D_];
__device__ __half g_xlo[(size_t)NTOK_ * D_];
__device__ __half g_ahi[(size_t)NPAIR_ * H_];
__device__ __half g_alo[(size_t)NPAIR_ * H_];
__device__ __half g_w1h[(size_t)E_ * H2_ * D_];              // W1^T [e][n][k]
__device__ __half g_w2h[(size_t)E_ * D_ * H_];               // W2^T [e][n][k]

// ---------------- kernel 0/1: zero + route -----------------------------------
__global__ void __launch_bounds__(256) zero_kernel(float4* __restrict__ out) {
    int i = blockIdx.x * 256 + threadIdx.x;
    out[i] = make_float4(0.f, 0.f, 0.f, 0.f);
    if (blockIdx.x == 0 && threadIdx.x < E_) g_cnt[threadIdx.x] = 0;
}
__global__ void __launch_bounds__(256) route_kernel(const int* __restrict__ idx) {
    int i = blockIdx.x * 256 + threadIdx.x;
    if (i < NPAIR_) {
        int e = idx[i];
        int pos = atomicAdd(&g_cnt[e], 1);
        g_perm[e * NPAIR_ + pos] = i;
    }
}

// ---------------- kernel 2: convert x -> fp16 hi/lo --------------------------
__global__ void __launch_bounds__(256) cvt_x_kernel(const float4* __restrict__ x) {
    int i = blockIdx.x * 256 + threadIdx.x;              // 512K float4
    float4 v = x[i];
    __half hx = __float2half_rn(v.x), hy = __float2half_rn(v.y);
    __half hz = __float2half_rn(v.z), hw = __float2half_rn(v.w);
    __half lx = __float2half_rn(v.x - __half2float(hx));
    __half ly = __float2half_rn(v.y - __half2float(hy));
    __half lz = __float2half_rn(v.z - __half2float(hz));
    __half lw = __float2half_rn(v.w - __half2float(hw));
    ((__half2*)g_xhi)[2 * i]     = __halves2half2(hx, hy);
    ((__half2*)g_xhi)[2 * i + 1] = __halves2half2(hz, hw);
    ((__half2*)g_xlo)[2 * i]     = __halves2half2(lx, ly);
    ((__half2*)g_xlo)[2 * i + 1] = __halves2half2(lz, lw);
}

// ---------------- kernel 3: transpose + cvt W -> [e][n][k] fp16 --------------
__global__ void transpose_cvt_kernel(const float* __restrict__ src, int which,
                                     int K, int N) {
    __shared__ float t[32][33];
    __half* dh = (which == 1) ? g_w1h : g_w2h;
    int e = blockIdx.z;
    const float* s = src + (size_t)e * K * N;
    size_t dbase = (size_t)e * K * N;
    int n0 = blockIdx.x * 32, k0 = blockIdx.y * 32;
    #pragma unroll
    for (int r = 0; r < 32; r += 8)
        t[threadIdx.y + r][threadIdx.x] = s[(size_t)(k0 + threadIdx.y + r) * N + n0 + threadIdx.x];
    __syncthreads();
    #pragma unroll
    for (int r = 0; r < 32; r += 8) {
        int n = n0 + threadIdx.y + r;
        float v = t[threadIdx.x][threadIdx.y + r];
        dh[dbase + (size_t)n * K + k0 + threadIdx.x] = __float2half_rn(v);
    }
}

// ---------------- kernel 5: silu + convert to fp16 hi/lo ---------------------
__global__ void __launch_bounds__(256) silu_cvt_kernel() {
    int i = blockIdx.x * 256 + threadIdx.x;              // NPAIR*H/4 = 1M
    int p = i >> 8;
    int j = (i & 255) << 2;
    float4 hv = *(const float4*)(g_hg + (size_t)p * H2_ + j);
    float4 gv = *(const float4*)(g_hg + (size_t)p * H2_ + H_ + j);
    float a0 = hv.x * gv.x / (1.f + expf(-gv.x));
    float a1 = hv.y * gv.y / (1.f + expf(-gv.y));
    float a2 = hv.z * gv.z / (1.f + expf(-gv.z));
    float a3 = hv.w * gv.w / (1.f + expf(-gv.w));
    __half h0 = __float2half_rn(a0), h1 = __float2half_rn(a1);
    __half h2 = __float2half_rn(a2), h3 = __float2half_rn(a3);
    __half l0 = __float2half_rn(a0 - __half2float(h0));
    __half l1 = __float2half_rn(a1 - __half2float(h1));
    __half l2 = __float2half_rn(a2 - __half2float(h2));
    __half l3 = __float2half_rn(a3 - __half2float(h3));
    size_t o = ((size_t)p * H_ + j) >> 1;
    ((__half2*)g_ahi)[o]     = __halves2half2(h0, h1);
    ((__half2*)g_ahi)[o + 1] = __halves2half2(h2, h3);
    ((__half2*)g_alo)[o]     = __halves2half2(l0, l1);
    ((__half2*)g_alo)[o + 1] = __halves2half2(l2, l3);
}

// ---------------- warp-level helpers ------------------------------------------
__device__ __forceinline__ void mma16816(float* c, const uint32_t* a, const uint32_t* b) {
    asm volatile(
        "mma.sync.aligned.m16n8k16.row.col.f32.f16.f16.f32 "
        "{%0,%1,%2,%3}, {%4,%5,%6,%7}, {%8,%9}, {%0,%1,%2,%3};"
        : "+f"(c[0]), "+f"(c[1]), "+f"(c[2]), "+f"(c[3])
        : "r"(a[0]), "r"(a[1]), "r"(a[2]), "r"(a[3]), "r"(b[0]), "r"(b[1]));
}
__device__ __forceinline__ void ldsm4(uint32_t* d, uint32_t a) {
    asm volatile("ldmatrix.sync.aligned.m8n8.x4.shared.b16 {%0,%1,%2,%3}, [%4];"
                 : "=r"(d[0]), "=r"(d[1]), "=r"(d[2]), "=r"(d[3]) : "r"(a));
}
__device__ __forceinline__ void cpasync16(uint32_t dst, const void* src, int sz) {
    asm volatile("cp.async.cg.shared.global [%0], [%1], 16, %2;"
                 :: "r"(dst), "l"(src), "r"(sz) : "memory");
}
__device__ __forceinline__ uint32_t smem_u32(const void* p) {
    uint32_t a;
    asm("{ .reg .u64 t; cvta.to.shared.u64 t, %1; cvt.u32.u64 %0, t; }" : "=r"(a) : "l"(p));
    return a;
}

// ---------------- GEMM: 128x128 CTA, 8 warps (2x4), warp 64x32, KC=64 --------
// SMEM: rowoff[128] @0; 3 stages @1024 + s*49152:
//   each stage: Ah(16K) Al(16K) Bh(16K); rows of 128B, 16B-chunk swizzle
//   (chunk ^ (row&7)) -> conflict-free cp.async stores + ldmatrix reads.
#define KC       64
#define STAGE_B  49152
#define NSTAGE   3
#define SMEM_DYN (1024 + NSTAGE * STAGE_B)

__global__ void __launch_bounds__(256, 1) moe_gemm_kernel(
    const float* __restrict__ pgate, float* __restrict__ out, int mode, int Ntot)
{
    const int e     = blockIdx.z;
    const int cnt   = g_cnt[e];
    const int mTile = blockIdx.y;
    if (mTile * 128 >= cnt) return;
    const int nTile = blockIdx.x;

    extern __shared__ char smem[];
    int* rowoff = (int*)smem;
    const uint32_t sbase = smem_u32(smem);

    const int tid  = threadIdx.x;
    const int wid  = tid >> 5;
    const int lane = tid & 31;
    const int wm   = wid & 1;          // 0..1
    const int wn   = wid >> 1;         // 0..3

    const __half* Ahi = (mode == 1) ? g_xhi : g_ahi;
    const __half* Alo = (mode == 1) ? g_xlo : g_alo;
    const __half* Bh  = (mode == 1) ? g_w1h : g_w2h;
    Bh += ((size_t)e * Ntot + (size_t)nTile * 128) * 1024;

    if (tid < 128) {
        int rg = mTile * 128 + tid;
        int off = -1;
        if (rg < cnt) {
            int pair = g_perm[e * NPAIR_ + rg];
            off = (mode == 1) ? ((pair >> 1) << 10) : (pair << 10);
        }
        rowoff[tid] = off;
    }
    __syncthreads();

    // ---- cp.async stage loader: thread t -> row r=t/2, 4 16B chunks/array ---
    const int lr  = tid >> 1;
    const int lcb = (tid & 1) * 4;
    const int lrx = lr & 7;
    auto issue_stage = [&](int c) {
        const int k0 = c * KC;
        const uint32_t stb = sbase + 1024 + (c % NSTAGE) * STAGE_B;
        const uint32_t dA = stb + lr * 128;
        int ao = rowoff[lr];
        int sz = (ao >= 0) ? 16 : 0;
        const __half* aph = Ahi + (ao >= 0 ? ao : 0) + k0 + lcb * 8;
        const __half* apl = Alo + (ao >= 0 ? ao : 0) + k0 + lcb * 8;
        const __half* bph = Bh + (size_t)lr * 1024 + k0 + lcb * 8;
        #pragma unroll
        for (int i = 0; i < 4; i++) {
            uint32_t sw = (uint32_t)(((lcb + i) ^ lrx) << 4);
            cpasync16(dA + sw,         aph + i * 8, sz);
            cpasync16(dA + 16384 + sw, apl + i * 8, sz);
            cpasync16(dA + 32768 + sw, bph + i * 8, 16);
        }
        asm volatile("cp.async.commit_group;" ::: "memory");
    };

    // ---- per-lane ldmatrix address bases ------------------------------------
    const int g  = lane >> 3;
    const int r8 = lane & 7;
    uint32_t aRowOff[4], bRowOff[2];
    #pragma unroll
    for (int mf = 0; mf < 4; mf++)
        aRowOff[mf] = (uint32_t)((wm * 64 + mf * 16 + (g & 1) * 8 + r8) * 128);
    #pragma unroll
    for (int j = 0; j < 2; j++)
        bRowOff[j] = (uint32_t)((wn * 32 + j * 16 + (g >> 1) * 8 + r8) * 128);
    const int acadd = g >> 1;
    const int bcadd = g & 1;

    float acc[4][4][4];
    #pragma unroll
    for (int i = 0; i < 4; i++)
        #pragma unroll
        for (int j = 0; j < 4; j++)
            #pragma unroll
            for (int q = 0; q < 4; q++) acc[i][j][q] = 0.f;

    issue_stage(0);
    issue_stage(1);

    const int NCH = 1024 / KC;   // 16
    for (int c = 0; c < NCH; c++) {
        if (c < NCH - 1) asm volatile("cp.async.wait_group 1;" ::: "memory");
        else             asm volatile("cp.async.wait_group 0;" ::: "memory");
        __syncthreads();
        if (c + 2 < NCH) issue_stage(c + 2);

        const uint32_t stb = sbase + 1024 + (c % NSTAGE) * STAGE_B;
        #pragma unroll
        for (int s = 0; s < 4; s++) {
            uint32_t ah[4][4], al[4][4], bh[2][4];
            const uint32_t asw = (uint32_t)((((s * 2 + acadd) ^ r8) << 4));
            const uint32_t bsw = (uint32_t)((((s * 2 + bcadd) ^ r8) << 4));
            #pragma unroll
            for (int mf = 0; mf < 4; mf++) {
                ldsm4(ah[mf], stb + aRowOff[mf] + asw);
                ldsm4(al[mf], stb + 16384 + aRowOff[mf] + asw);
            }
            #pragma unroll
            for (int j = 0; j < 2; j++)
                ldsm4(bh[j], stb + 32768 + bRowOff[j] + bsw);
            #pragma unroll
            for (int mf = 0; mf < 4; mf++)
                #pragma unroll
                for (int nf = 0; nf < 4; nf++) {
                    const int jj = nf >> 1, hh = nf & 1;
                    uint32_t bhp[2] = { bh[jj][2 * hh], bh[jj][2 * hh + 1] };
                    mma16816(acc[mf][nf], ah[mf], bhp);
                    mma16816(acc[mf][nf], al[mf], bhp);
                }
        }
    }

    // ---- epilogue ----
    const int gr  = lane >> 2;
    const int lc2 = (lane & 3) * 2;
    #pragma unroll
    for (int mf = 0; mf < 4; mf++) {
        #pragma unroll
        for (int half = 0; half < 2; half++) {
            int r   = wm * 64 + mf * 16 + gr + half * 8;
            int rg2 = mTile * 128 + r;
            if (rg2 < cnt) {
                int pair = g_perm[e * NPAIR_ + rg2];
                if (mode == 1) {
                    float* dst = g_hg + (size_t)pair * H2_ + (size_t)nTile * 128;
                    #pragma unroll
                    for (int nf = 0; nf < 4; nf++) {
                        int n = wn * 32 + nf * 8 + lc2;
                        *(float2*)(dst + n) = make_float2(acc[mf][nf][half * 2],
                                                          acc[mf][nf][half * 2 + 1]);
                    }
                } else {
                    float pc = pgate[pair];
                    float* dst = out + (size_t)(pair >> 1) * D_ + (size_t)nTile * 128;
                    #pragma unroll
                    for (int nf = 0; nf < 4; nf++) {
                        int n = wn * 32 + nf * 8 + lc2;
                        atomicAdd(dst + n,     acc[mf][nf][half * 2]     * pc);
                        atomicAdd(dst + n + 1, acc[mf][nf][half * 2 + 1] * pc);
                    }
                }
            }
        }
    }
}

// ---------------- launch ------------------------------------------------------
extern "C" void kernel_launch(void* const* d_in, const int* in_sizes, int n_in,
                              void* d_out, int out_size) {
    const float* x   = (const float*)d_in[0];   // [2,1024,1024] f32
    const float* p   = (const float*)d_in[1];   // [2048,2]      f32
    const int*   idx = (const int*)  d_in[2];   // [2048,2]      int32
    const float* W1  = (const float*)d_in[3];   // [8,1024,2048] f32
    const float* W2  = (const float*)d_in[4];   // [8,1024,1024] f32
    float*       out = (float*)d_out;           // [2,1024,1024] f32
    (void)in_sizes; (void)n_in; (void)out_size;

    cudaFuncSetAttribute(moe_gemm_kernel,
                         cudaFuncAttributeMaxDynamicSharedMemorySize, SMEM_DYN);

    zero_kernel <<<2048, 256>>>((float4*)out);
    route_kernel<<<16,   256>>>(idx);
    cvt_x_kernel<<<2048, 256>>>((const float4*)x);
    transpose_cvt_kernel<<<dim3(H2_/32, D_/32, E_), dim3(32, 8)>>>(W1, 1, D_, H2_);
    transpose_cvt_kernel<<<dim3(H_/32,  H_/32, E_), dim3(32, 8)>>>(W2, 2, H_, H_);
    moe_gemm_kernel<<<dim3(H2_/128, NPAIR_/128, E_), 256, SMEM_DYN>>>(p, out, 1, H2_);
    silu_cvt_kernel<<<4096, 256>>>();
    moe_gemm_kernel<<<dim3(D_/128, NPAIR_/128, E_), 256, SMEM_DYN>>>(p, out, 2, D_);
}

// round 6
// speedup vs baseline: 3.2204x; 1.3830x over previous
#include <cuda_runtime.h>
#include <cuda_fp16.h>
#include <cstdint>
#include <math.h>

// ---------------- problem constants -----------------------------------------
#define E_      8
#define D_      1024
#define H_      1024
#define H2_     2048
#define NTOK_   2048
#define NPAIR_  4096

// ---------------- scratch (__device__ globals; no allocations) --------------
__device__ int   g_cnt[E_];
__device__ int   g_perm[E_ * NPAIR_];
__device__ __half g_xh[(size_t)NTOK_ * D_];                  // x fp16
__device__ __half g_ah[(size_t)NPAIR_ * H_];                 // act fp16
__device__ __half g_w1h[(size_t)E_ * H2_ * D_];              // W1^T interleaved [e][n'][k]
__device__ __half g_w2h[(size_t)E_ * D_ * H_];               // W2^T [e][n][k]

// ---------------- kernel 0/1: zero + route -----------------------------------
__global__ void __launch_bounds__(256) zero_kernel(float4* __restrict__ out) {
    int i = blockIdx.x * 256 + threadIdx.x;
    out[i] = make_float4(0.f, 0.f, 0.f, 0.f);
    if (blockIdx.x == 0 && threadIdx.x < E_) g_cnt[threadIdx.x] = 0;
}
__global__ void __launch_bounds__(256) route_kernel(const int* __restrict__ idx) {
    int i = blockIdx.x * 256 + threadIdx.x;
    if (i < NPAIR_) {
        int e = idx[i];
        int pos = atomicAdd(&g_cnt[e], 1);
        g_perm[e * NPAIR_ + pos] = i;
    }
}

// ---------------- kernel 2: convert x -> fp16 --------------------------------
__global__ void __launch_bounds__(256) cvt_x_kernel(const float4* __restrict__ x) {
    int i = blockIdx.x * 256 + threadIdx.x;              // 512K float4
    float4 v = x[i];
    ((__half2*)g_xh)[2 * i]     = __halves2half2(__float2half_rn(v.x), __float2half_rn(v.y));
    ((__half2*)g_xh)[2 * i + 1] = __halves2half2(__float2half_rn(v.z), __float2half_rn(v.w));
}

// ---------------- kernel 3: transpose + cvt W -> fp16 ------------------------
// which==1: W1 -> g_w1h with h/g row interleaving: logical col n<1024 (h part)
//           goes to row 2n; n>=1024 (g part) goes to row 2(n-1024)+1.
// which==2: W2 -> g_w2h plain transpose.
__global__ void transpose_cvt_kernel(const float* __restrict__ src, int which,
                                     int K, int N) {
    __shared__ float t[32][33];
    __half* dh = (which == 1) ? g_w1h : g_w2h;
    int e = blockIdx.z;
    const float* s = src + (size_t)e * K * N;
    size_t dbase = (size_t)e * K * N;
    int n0 = blockIdx.x * 32, k0 = blockIdx.y * 32;
    #pragma unroll
    for (int r = 0; r < 32; r += 8)
        t[threadIdx.y + r][threadIdx.x] = s[(size_t)(k0 + threadIdx.y + r) * N + n0 + threadIdx.x];
    __syncthreads();
    #pragma unroll
    for (int r = 0; r < 32; r += 8) {
        int n = n0 + threadIdx.y + r;
        int np = (which == 1) ? ((n < 1024) ? (2 * n) : (2 * (n - 1024) + 1)) : n;
        float v = t[threadIdx.x][threadIdx.y + r];
        dh[dbase + (size_t)np * K + k0 + threadIdx.x] = __float2half_rn(v);
    }
}

// ---------------- warp-level helpers ------------------------------------------
__device__ __forceinline__ void mma16816(float* c, const uint32_t* a, const uint32_t* b) {
    asm volatile(
        "mma.sync.aligned.m16n8k16.row.col.f32.f16.f16.f32 "
        "{%0,%1,%2,%3}, {%4,%5,%6,%7}, {%8,%9}, {%0,%1,%2,%3};"
        : "+f"(c[0]), "+f"(c[1]), "+f"(c[2]), "+f"(c[3])
        : "r"(a[0]), "r"(a[1]), "r"(a[2]), "r"(a[3]), "r"(b[0]), "r"(b[1]));
}
__device__ __forceinline__ void ldsm4(uint32_t* d, uint32_t a) {
    asm volatile("ldmatrix.sync.aligned.m8n8.x4.shared.b16 {%0,%1,%2,%3}, [%4];"
                 : "=r"(d[0]), "=r"(d[1]), "=r"(d[2]), "=r"(d[3]) : "r"(a));
}
__device__ __forceinline__ void cpasync16(uint32_t dst, const void* src, int sz) {
    asm volatile("cp.async.cg.shared.global [%0], [%1], 16, %2;"
                 :: "r"(dst), "l"(src), "r"(sz) : "memory");
}
__device__ __forceinline__ uint32_t smem_u32(const void* p) {
    uint32_t a;
    asm("{ .reg .u64 t; cvta.to.shared.u64 t, %1; cvt.u32.u64 %0, t; }" : "=r"(a) : "l"(p));
    return a;
}

// ---------------- GEMM: 128x128 CTA, 8 warps (2x4), warp 64x32, KC=64 --------
// SMEM: rowoff[128] @0; 3 stages @1024 + s*32768: A(16K) B(16K); 128B rows,
// 16B-chunk swizzle (chunk ^ (row&7)) -> conflict-free cp.async + ldmatrix.
//
// mode 1: A = gathered x fp16; B = interleaved W1^T rows (h at even, g at odd).
//         Accumulator col pairs (2j, 2j+1) = (h_j, g_j); epilogue computes
//         a = h * silu(g) in-register and writes fp16 act (64 cols per nTile).
// mode 2: A = gathered act fp16; B = W2^T; epilogue p-weighted atomicAdd.
#define KC       64
#define STAGE_B  32768
#define NSTAGE   3
#define SMEM_DYN (1024 + NSTAGE * STAGE_B)

__global__ void __launch_bounds__(256, 1) moe_gemm_kernel(
    const float* __restrict__ pgate, float* __restrict__ out, int mode, int Ntot)
{
    const int e     = blockIdx.z;
    const int cnt   = g_cnt[e];
    const int mTile = blockIdx.y;
    if (mTile * 128 >= cnt) return;
    const int nTile = blockIdx.x;

    extern __shared__ char smem[];
    int* rowoff = (int*)smem;
    const uint32_t sbase = smem_u32(smem);

    const int tid  = threadIdx.x;
    const int wid  = tid >> 5;
    const int lane = tid & 31;
    const int wm   = wid & 1;          // 0..1
    const int wn   = wid >> 1;         // 0..3

    const __half* A  = (mode == 1) ? g_xh  : g_ah;
    const __half* Bh = (mode == 1) ? g_w1h : g_w2h;
    Bh += ((size_t)e * Ntot + (size_t)nTile * 128) * 1024;

    if (tid < 128) {
        int rg = mTile * 128 + tid;
        int off = -1;
        if (rg < cnt) {
            int pair = g_perm[e * NPAIR_ + rg];
            off = (mode == 1) ? ((pair >> 1) << 10) : (pair << 10);
        }
        rowoff[tid] = off;
    }
    __syncthreads();

    // ---- cp.async stage loader: thread t -> row r=t/2, 4 16B chunks/array ---
    const int lr  = tid >> 1;
    const int lcb = (tid & 1) * 4;
    const int lrx = lr & 7;
    auto issue_stage = [&](int c) {
        const int k0 = c * KC;
        const uint32_t stb = sbase + 1024 + (c % NSTAGE) * STAGE_B;
        const uint32_t dA = stb + lr * 128;
        int ao = rowoff[lr];
        int sz = (ao >= 0) ? 16 : 0;
        const __half* aph = A  + (ao >= 0 ? ao : 0) + k0 + lcb * 8;
        const __half* bph = Bh + (size_t)lr * 1024 + k0 + lcb * 8;
        #pragma unroll
        for (int i = 0; i < 4; i++) {
            uint32_t sw = (uint32_t)(((lcb + i) ^ lrx) << 4);
            cpasync16(dA + sw,         aph + i * 8, sz);
            cpasync16(dA + 16384 + sw, bph + i * 8, 16);
        }
        asm volatile("cp.async.commit_group;" ::: "memory");
    };

    // ---- per-lane ldmatrix address bases ------------------------------------
    const int g  = lane >> 3;
    const int r8 = lane & 7;
    uint32_t aRowOff[4], bRowOff[2];
    #pragma unroll
    for (int mf = 0; mf < 4; mf++)
        aRowOff[mf] = (uint32_t)((wm * 64 + mf * 16 + (g & 1) * 8 + r8) * 128);
    #pragma unroll
    for (int j = 0; j < 2; j++)
        bRowOff[j] = (uint32_t)((wn * 32 + j * 16 + (g >> 1) * 8 + r8) * 128);
    const int acadd = g >> 1;
    const int bcadd = g & 1;

    float acc[4][4][4];
    #pragma unroll
    for (int i = 0; i < 4; i++)
        #pragma unroll
        for (int j = 0; j < 4; j++)
            #pragma unroll
            for (int q = 0; q < 4; q++) acc[i][j][q] = 0.f;

    issue_stage(0);
    issue_stage(1);

    const int NCH = 1024 / KC;   // 16
    for (int c = 0; c < NCH; c++) {
        if (c < NCH - 1) asm volatile("cp.async.wait_group 1;" ::: "memory");
        else             asm volatile("cp.async.wait_group 0;" ::: "memory");
        __syncthreads();
        if (c + 2 < NCH) issue_stage(c + 2);

        const uint32_t stb = sbase + 1024 + (c % NSTAGE) * STAGE_B;
        #pragma unroll
        for (int s = 0; s < 4; s++) {
            uint32_t ah[4][4], bh[2][4];
            const uint32_t asw = (uint32_t)((((s * 2 + acadd) ^ r8) << 4));
            const uint32_t bsw = (uint32_t)((((s * 2 + bcadd) ^ r8) << 4));
            #pragma unroll
            for (int mf = 0; mf < 4; mf++)
                ldsm4(ah[mf], stb + aRowOff[mf] + asw);
            #pragma unroll
            for (int j = 0; j < 2; j++)
                ldsm4(bh[j], stb + 16384 + bRowOff[j] + bsw);
            #pragma unroll
            for (int mf = 0; mf < 4; mf++)
                #pragma unroll
                for (int nf = 0; nf < 4; nf++) {
                    const int jj = nf >> 1, hh = nf & 1;
                    uint32_t bhp[2] = { bh[jj][2 * hh], bh[jj][2 * hh + 1] };
                    mma16816(acc[mf][nf], ah[mf], bhp);
                }
        }
    }

    // ---- epilogue ----
    const int gr  = lane >> 2;
    const int lc2 = (lane & 3) * 2;
    #pragma unroll
    for (int mf = 0; mf < 4; mf++) {
        #pragma unroll
        for (int half = 0; half < 2; half++) {
            int r   = wm * 64 + mf * 16 + gr + half * 8;
            int rg2 = mTile * 128 + r;
            if (rg2 < cnt) {
                int pair = g_perm[e * NPAIR_ + rg2];
                if (mode == 1) {
                    // interleaved: acc col pair (lc2, lc2+1) = (h, g) for
                    // logical act col nTile*64 + (wn*32 + nf*8 + lc2)/2
                    __half* dst = g_ah + (size_t)pair * H_ + (size_t)nTile * 64;
                    #pragma unroll
                    for (int nf = 0; nf < 4; nf++) {
                        float h = acc[mf][nf][half * 2];
                        float gg = acc[mf][nf][half * 2 + 1];
                        float a = h * gg / (1.f + __expf(-gg));
                        int n = (wn * 32 + nf * 8 + lc2) >> 1;
                        dst[n] = __float2half_rn(a);
                    }
                } else {
                    float pc = pgate[pair];
                    float* dst = out + (size_t)(pair >> 1) * D_ + (size_t)nTile * 128;
                    #pragma unroll
                    for (int nf = 0; nf < 4; nf++) {
                        int n = wn * 32 + nf * 8 + lc2;
                        atomicAdd(dst + n,     acc[mf][nf][half * 2]     * pc);
                        atomicAdd(dst + n + 1, acc[mf][nf][half * 2 + 1] * pc);
                    }
                }
            }
        }
    }
}

// ---------------- launch ------------------------------------------------------
extern "C" void kernel_launch(void* const* d_in, const int* in_sizes, int n_in,
                              void* d_out, int out_size) {
    const float* x   = (const float*)d_in[0];   // [2,1024,1024] f32
    const float* p   = (const float*)d_in[1];   // [2048,2]      f32
    const int*   idx = (const int*)  d_in[2];   // [2048,2]      int32
    const float* W1  = (const float*)d_in[3];   // [8,1024,2048] f32
    const float* W2  = (const float*)d_in[4];   // [8,1024,1024] f32
    float*       out = (float*)d_out;           // [2,1024,1024] f32
    (void)in_sizes; (void)n_in; (void)out_size;

    cudaFuncSetAttribute(moe_gemm_kernel,
                         cudaFuncAttributeMaxDynamicSharedMemorySize, SMEM_DYN);

    zero_kernel <<<2048, 256>>>((float4*)out);
    route_kernel<<<16,   256>>>(idx);
    cvt_x_kernel<<<2048, 256>>>((const float4*)x);
    transpose_cvt_kernel<<<dim3(H2_/32, D_/32, E_), dim3(32, 8)>>>(W1, 1, D_, H2_);
    transpose_cvt_kernel<<<dim3(H_/32,  H_/32, E_), dim3(32, 8)>>>(W2, 2, H_, H_);
    moe_gemm_kernel<<<dim3(H2_/128, NPAIR_/128, E_), 256, SMEM_DYN>>>(p, out, 1, H2_);
    moe_gemm_kernel<<<dim3(D_/128,  NPAIR_/128, E_), 256, SMEM_DYN>>>(p, out, 2, D_);
}

// round 7
// speedup vs baseline: 3.7175x; 1.1543x over previous
#include <cuda_runtime.h>
#include <cuda_fp16.h>
#include <cstdint>
#include <math.h>

// ---------------- problem constants -----------------------------------------
#define E_      8
#define D_      1024
#define H_      1024
#define H2_     2048
#define NTOK_   2048
#define NPAIR_  4096

// ---------------- scratch (__device__ globals; no allocations) --------------
__device__ int   g_cnt[E_];
__device__ int   g_perm[E_ * NPAIR_];
__device__ __half g_xh[(size_t)NTOK_ * D_];                  // x fp16
__device__ __half g_ah[(size_t)NPAIR_ * H_];                 // act fp16
__device__ __half g_w1h[(size_t)E_ * H2_ * D_];              // W1^T interleaved [e][n'][k]
__device__ __half g_w2h[(size_t)E_ * D_ * H_];               // W2^T [e][n][k]

// ---------------- kernel 0/1: zero + route -----------------------------------
__global__ void __launch_bounds__(256) zero_kernel(float4* __restrict__ out) {
    int i = blockIdx.x * 256 + threadIdx.x;
    out[i] = make_float4(0.f, 0.f, 0.f, 0.f);
    if (blockIdx.x == 0 && threadIdx.x < E_) g_cnt[threadIdx.x] = 0;
}
__global__ void __launch_bounds__(256) route_kernel(const int* __restrict__ idx) {
    int i = blockIdx.x * 256 + threadIdx.x;
    if (i < NPAIR_) {
        int e = idx[i];
        int pos = atomicAdd(&g_cnt[e], 1);
        g_perm[e * NPAIR_ + pos] = i;
    }
}

// ---------------- kernel 2: convert x -> fp16 --------------------------------
__global__ void __launch_bounds__(256) cvt_x_kernel(const float4* __restrict__ x) {
    int i = blockIdx.x * 256 + threadIdx.x;              // 512K float4
    float4 v = x[i];
    ((__half2*)g_xh)[2 * i]     = __halves2half2(__float2half_rn(v.x), __float2half_rn(v.y));
    ((__half2*)g_xh)[2 * i + 1] = __halves2half2(__float2half_rn(v.z), __float2half_rn(v.w));
}

// ---------------- kernel 3: transpose + cvt W -> fp16 ------------------------
// which==1: W1 -> g_w1h with h/g row interleaving: logical col n<1024 (h part)
//           goes to row 2n; n>=1024 (g part) goes to row 2(n-1024)+1.
// which==2: W2 -> g_w2h plain transpose.
__global__ void transpose_cvt_kernel(const float* __restrict__ src, int which,
                                     int K, int N) {
    __shared__ float t[32][33];
    __half* dh = (which == 1) ? g_w1h : g_w2h;
    int e = blockIdx.z;
    const float* s = src + (size_t)e * K * N;
    size_t dbase = (size_t)e * K * N;
    int n0 = blockIdx.x * 32, k0 = blockIdx.y * 32;
    #pragma unroll
    for (int r = 0; r < 32; r += 8)
        t[threadIdx.y + r][threadIdx.x] = s[(size_t)(k0 + threadIdx.y + r) * N + n0 + threadIdx.x];
    __syncthreads();
    #pragma unroll
    for (int r = 0; r < 32; r += 8) {
        int n = n0 + threadIdx.y + r;
        int np = (which == 1) ? ((n < 1024) ? (2 * n) : (2 * (n - 1024) + 1)) : n;
        float v = t[threadIdx.x][threadIdx.y + r];
        dh[dbase + (size_t)np * K + k0 + threadIdx.x] = __float2half_rn(v);
    }
}

// ---------------- warp-level helpers ------------------------------------------
__device__ __forceinline__ void mma16816(float* c, const uint32_t* a, const uint32_t* b) {
    asm volatile(
        "mma.sync.aligned.m16n8k16.row.col.f32.f16.f16.f32 "
        "{%0,%1,%2,%3}, {%4,%5,%6,%7}, {%8,%9}, {%0,%1,%2,%3};"
        : "+f"(c[0]), "+f"(c[1]), "+f"(c[2]), "+f"(c[3])
        : "r"(a[0]), "r"(a[1]), "r"(a[2]), "r"(a[3]), "r"(b[0]), "r"(b[1]));
}
__device__ __forceinline__ void ldsm4(uint32_t* d, uint32_t a) {
    asm volatile("ldmatrix.sync.aligned.m8n8.x4.shared.b16 {%0,%1,%2,%3}, [%4];"
                 : "=r"(d[0]), "=r"(d[1]), "=r"(d[2]), "=r"(d[3]) : "r"(a));
}
__device__ __forceinline__ void cpasync16(uint32_t dst, const void* src, int sz) {
    asm volatile("cp.async.cg.shared.global [%0], [%1], 16, %2;"
                 :: "r"(dst), "l"(src), "r"(sz) : "memory");
}
__device__ __forceinline__ uint32_t smem_u32(const void* p) {
    uint32_t a;
    asm("{ .reg .u64 t; cvta.to.shared.u64 t, %1; cvt.u32.u64 %0, t; }" : "=r"(a) : "l"(p));
    return a;
}

// ---------------- GEMM: 128x128 CTA, 8 warps (2x4), warp 64x32, KC=64 --------
// SMEM: rowoff[128] @0; 3 stages @1024 + s*32768: A(16K) B(16K); 128B rows,
// 16B-chunk swizzle (chunk ^ (row&7)) -> conflict-free cp.async + ldmatrix.
// __launch_bounds__(256, 2): 2 CTAs/SM (194KB smem, <=128 regs) -> 4 warps/SMSP
// to cover LDSM->HMMA latency that 1 CTA/SM could not.
#define KC       64
#define STAGE_B  32768
#define NSTAGE   3
#define SMEM_DYN (1024 + NSTAGE * STAGE_B)

__global__ void __launch_bounds__(256, 2) moe_gemm_kernel(
    const float* __restrict__ pgate, float* __restrict__ out, int mode, int Ntot)
{
    const int e     = blockIdx.z;
    const int cnt   = g_cnt[e];
    const int mTile = blockIdx.y;
    if (mTile * 128 >= cnt) return;
    const int nTile = blockIdx.x;

    extern __shared__ char smem[];
    int* rowoff = (int*)smem;
    const uint32_t sbase = smem_u32(smem);

    const int tid  = threadIdx.x;
    const int wid  = tid >> 5;
    const int lane = tid & 31;
    const int wm   = wid & 1;          // 0..1
    const int wn   = wid >> 1;         // 0..3

    const __half* A  = (mode == 1) ? g_xh  : g_ah;
    const __half* Bh = (mode == 1) ? g_w1h : g_w2h;
    Bh += ((size_t)e * Ntot + (size_t)nTile * 128) * 1024;

    if (tid < 128) {
        int rg = mTile * 128 + tid;
        int off = -1;
        if (rg < cnt) {
            int pair = g_perm[e * NPAIR_ + rg];
            off = (mode == 1) ? ((pair >> 1) << 10) : (pair << 10);
        }
        rowoff[tid] = off;
    }
    __syncthreads();

    // ---- cp.async stage loader: thread t -> row r=t/2, 4 16B chunks/array ---
    const int lr  = tid >> 1;
    const int lcb = (tid & 1) * 4;
    const int lrx = lr & 7;
    auto issue_stage = [&](int c) {
        const int k0 = c * KC;
        const uint32_t stb = sbase + 1024 + (c % NSTAGE) * STAGE_B;
        const uint32_t dA = stb + lr * 128;
        int ao = rowoff[lr];
        int sz = (ao >= 0) ? 16 : 0;
        const __half* aph = A  + (ao >= 0 ? ao : 0) + k0 + lcb * 8;
        const __half* bph = Bh + (size_t)lr * 1024 + k0 + lcb * 8;
        #pragma unroll
        for (int i = 0; i < 4; i++) {
            uint32_t sw = (uint32_t)(((lcb + i) ^ lrx) << 4);
            cpasync16(dA + sw,         aph + i * 8, sz);
            cpasync16(dA + 16384 + sw, bph + i * 8, 16);
        }
        asm volatile("cp.async.commit_group;" ::: "memory");
    };

    // ---- per-lane ldmatrix address bases ------------------------------------
    const int g  = lane >> 3;
    const int r8 = lane & 7;
    uint32_t aRowOff[4], bRowOff[2];
    #pragma unroll
    for (int mf = 0; mf < 4; mf++)
        aRowOff[mf] = (uint32_t)((wm * 64 + mf * 16 + (g & 1) * 8 + r8) * 128);
    #pragma unroll
    for (int j = 0; j < 2; j++)
        bRowOff[j] = (uint32_t)((wn * 32 + j * 16 + (g >> 1) * 8 + r8) * 128);
    const int acadd = g >> 1;
    const int bcadd = g & 1;

    float acc[4][4][4];
    #pragma unroll
    for (int i = 0; i < 4; i++)
        #pragma unroll
        for (int j = 0; j < 4; j++)
            #pragma unroll
            for (int q = 0; q < 4; q++) acc[i][j][q] = 0.f;

    issue_stage(0);
    issue_stage(1);

    const int NCH = 1024 / KC;   // 16
    for (int c = 0; c < NCH; c++) {
        if (c < NCH - 1) asm volatile("cp.async.wait_group 1;" ::: "memory");
        else             asm volatile("cp.async.wait_group 0;" ::: "memory");
        __syncthreads();
        if (c + 2 < NCH) issue_stage(c + 2);

        const uint32_t stb = sbase + 1024 + (c % NSTAGE) * STAGE_B;
        #pragma unroll
        for (int s = 0; s < 4; s++) {
            uint32_t ah[4][4], bh[2][4];
            const uint32_t asw = (uint32_t)((((s * 2 + acadd) ^ r8) << 4));
            const uint32_t bsw = (uint32_t)((((s * 2 + bcadd) ^ r8) << 4));
            #pragma unroll
            for (int mf = 0; mf < 4; mf++)
                ldsm4(ah[mf], stb + aRowOff[mf] + asw);
            #pragma unroll
            for (int j = 0; j < 2; j++)
                ldsm4(bh[j], stb + 16384 + bRowOff[j] + bsw);
            #pragma unroll
            for (int mf = 0; mf < 4; mf++)
                #pragma unroll
                for (int nf = 0; nf < 4; nf++) {
                    const int jj = nf >> 1, hh = nf & 1;
                    uint32_t bhp[2] = { bh[jj][2 * hh], bh[jj][2 * hh + 1] };
                    mma16816(acc[mf][nf], ah[mf], bhp);
                }
        }
    }

    // ---- epilogue ----
    const int gr  = lane >> 2;
    const int lc2 = (lane & 3) * 2;
    #pragma unroll
    for (int mf = 0; mf < 4; mf++) {
        #pragma unroll
        for (int half = 0; half < 2; half++) {
            int r   = wm * 64 + mf * 16 + gr + half * 8;
            int rg2 = mTile * 128 + r;
            if (rg2 < cnt) {
                int pair = g_perm[e * NPAIR_ + rg2];
                if (mode == 1) {
                    // interleaved: acc col pair (lc2, lc2+1) = (h, g) for
                    // logical act col nTile*64 + (wn*32 + nf*8 + lc2)/2
                    __half* dst = g_ah + (size_t)pair * H_ + (size_t)nTile * 64;
                    #pragma unroll
                    for (int nf = 0; nf < 4; nf++) {
                        float h = acc[mf][nf][half * 2];
                        float gg = acc[mf][nf][half * 2 + 1];
                        float a = h * gg / (1.f + __expf(-gg));
                        int n = (wn * 32 + nf * 8 + lc2) >> 1;
                        dst[n] = __float2half_rn(a);
                    }
                } else {
                    float pc = pgate[pair];
                    float* dst = out + (size_t)(pair >> 1) * D_ + (size_t)nTile * 128;
                    #pragma unroll
                    for (int nf = 0; nf < 4; nf++) {
                        int n = wn * 32 + nf * 8 + lc2;
                        atomicAdd(dst + n,     acc[mf][nf][half * 2]     * pc);
                        atomicAdd(dst + n + 1, acc[mf][nf][half * 2 + 1] * pc);
                    }
                }
            }
        }
    }
}

// ---------------- launch ------------------------------------------------------
extern "C" void kernel_launch(void* const* d_in, const int* in_sizes, int n_in,
                              void* d_out, int out_size) {
    const float* x   = (const float*)d_in[0];   // [2,1024,1024] f32
    const float* p   = (const float*)d_in[1];   // [2048,2]      f32
    const int*   idx = (const int*)  d_in[2];   // [2048,2]      int32
    const float* W1  = (const float*)d_in[3];   // [8,1024,2048] f32
    const float* W2  = (const float*)d_in[4];   // [8,1024,1024] f32
    float*       out = (float*)d_out;           // [2,1024,1024] f32
    (void)in_sizes; (void)n_in; (void)out_size;

    cudaFuncSetAttribute(moe_gemm_kernel,
                         cudaFuncAttributeMaxDynamicSharedMemorySize, SMEM_DYN);

    zero_kernel <<<2048, 256>>>((float4*)out);
    route_kernel<<<16,   256>>>(idx);
    cvt_x_kernel<<<2048, 256>>>((const float4*)x);
    transpose_cvt_kernel<<<dim3(H2_/32, D_/32, E_), dim3(32, 8)>>>(W1, 1, D_, H2_);
    transpose_cvt_kernel<<<dim3(H_/32,  H_/32, E_), dim3(32, 8)>>>(W2, 2, H_, H_);
    moe_gemm_kernel<<<dim3(H2_/128, NPAIR_/128, E_), 256, SMEM_DYN>>>(p, out, 1, H2_);
    moe_gemm_kernel<<<dim3(D_/128,  NPAIR_/128, E_), 256, SMEM_DYN>>>(p, out, 2, D_);
}